// round 15
// baseline (speedup 1.0000x reference)
#include <cuda_runtime.h>
#include <cuda_fp16.h>
#include <cstdint>

#define GRID_W 32
#define NNODES 1024
#define BATCH 256
#define KDIM 256
#define NTILES 2048
#define NCTA 148

// Scratch (device globals: no allocations allowed)
__device__ __half g_b1[BATCH * NNODES * 256];          // agg1
__device__ __half g_b2[BATCH * NNODES * 256];          // t3
__device__ __half g_w[65536 + 32768];                  // fp16 W2|W3
__device__ float  g_part[32 * 2560];

// ---------------------------------------------------------------------------
// Stencil weights: adj = D^-1/2 (A+I) D^-1/2, deg in {3,4,5}
// ---------------------------------------------------------------------------
__device__ __forceinline__ float disv(int i, int j) {
    int deg = 1 + (i > 0) + (i < GRID_W - 1) + (j > 0) + (j < GRID_W - 1);
    return deg == 5 ? 0.4472135954999579f
         : (deg == 4 ? 0.5f : 0.5773502691896258f);
}
__device__ __forceinline__ float rowsumv(int i, int j) {
    float d = disv(i, j);
    float s = d;
    if (i > 0)          s += disv(i - 1, j);
    if (i < GRID_W - 1) s += disv(i + 1, j);
    if (j > 0)          s += disv(i, j - 1);
    if (j < GRID_W - 1) s += disv(i, j + 1);
    return d * s;
}
__device__ __forceinline__ void h8fma(float s[8], uint4 u, float w) {
    __half2 h0 = *(__half2*)&u.x, h1 = *(__half2*)&u.y;
    __half2 h2 = *(__half2*)&u.z, h3 = *(__half2*)&u.w;
    float2 f;
    f = __half22float2(h0); s[0] = fmaf(w, f.x, s[0]); s[1] = fmaf(w, f.y, s[1]);
    f = __half22float2(h1); s[2] = fmaf(w, f.x, s[2]); s[3] = fmaf(w, f.y, s[3]);
    f = __half22float2(h2); s[4] = fmaf(w, f.x, s[4]); s[5] = fmaf(w, f.y, s[5]);
    f = __half22float2(h3); s[6] = fmaf(w, f.x, s[6]); s[7] = fmaf(w, f.y, s[7]);
}
__device__ __forceinline__ void ldsm4(uint32_t r[4], uint32_t addr) {
    asm volatile("ldmatrix.sync.aligned.m8n8.x4.shared.b16 {%0,%1,%2,%3}, [%4];"
                 : "=r"(r[0]), "=r"(r[1]), "=r"(r[2]), "=r"(r[3]) : "r"(addr));
}
__device__ __forceinline__ void cpa16(uint32_t dst, const void* src) {
    asm volatile("cp.async.cg.shared.global [%0], [%1], 16;" :: "r"(dst), "l"(src));
}

// ---------------------------------------------------------------------------
// Pre-convert W2|W3 fp32 -> fp16 (Wc stays fp32, read directly)
// ---------------------------------------------------------------------------
__global__ void convert_w_kernel(const float* __restrict__ W2,
                                 const float* __restrict__ W3,
                                 __half* __restrict__ o) {
    int i = blockIdx.x * 256 + threadIdx.x;
    if (i < 65536) o[i] = __float2half(W2[i]);
    if (i < 32768) o[65536 + i] = __float2half(W3[i]);
}

// ---------------------------------------------------------------------------
// Layer 1 fused through aggregation: agg1 = adj @ relu(adj@(x~W1)+rs*b1)
// ---------------------------------------------------------------------------
__global__ void layer1_kernel(const float* __restrict__ x,
                              const float* __restrict__ W1,
                              const float* __restrict__ b1,
                              __half* __restrict__ out) {
    const int gr = blockIdx.x, b = blockIdx.y, t = threadIdx.x;
    __shared__ float aggg[3][32][3];
    __shared__ float rs_s[3][32];
    __shared__ __half hstage[32][256];

    if (t < 96) {
        const int f = t >> 5, gc = t & 31;
        #pragma unroll
        for (int r = 0; r < 3; ++r) {
            int row = gr - 1 + r;
            float v = 0.f;
            if (row >= 0 && row < GRID_W) {
                const float* xp = x + ((size_t)(b * 3 + f)) * NNODES;
                float dm = disv(row, gc);
                float a = dm * xp[row * 32 + gc];
                if (row > 0)  a = fmaf(disv(row - 1, gc), xp[(row - 1) * 32 + gc], a);
                if (row < 31) a = fmaf(disv(row + 1, gc), xp[(row + 1) * 32 + gc], a);
                if (gc > 0)   a = fmaf(disv(row, gc - 1), xp[row * 32 + gc - 1], a);
                if (gc < 31)  a = fmaf(disv(row, gc + 1), xp[row * 32 + gc + 1], a);
                v = dm * a;
            }
            aggg[r][gc][f] = v;
            if (f == 0) rs_s[r][gc] = (row >= 0 && row < GRID_W) ? rowsumv(row, gc) : 0.f;
        }
    }
    __syncthreads();

    const float w0 = W1[t * 3 + 0], w1 = W1[t * 3 + 1], w2 = W1[t * 3 + 2];
    const float bb = b1[t];

    auto hval = [&](int r, int gc) {
        float v = fmaf(aggg[r][gc][0], w0,
                  fmaf(aggg[r][gc][1], w1,
                  fmaf(aggg[r][gc][2], w2, rs_s[r][gc] * bb)));
        return fmaxf(v, 0.f);
    };

    float hc_prev = 0.f, hc_cur = hval(1, 0), hc_next;
    #pragma unroll 4
    for (int gc = 0; gc < 32; ++gc) {
        hc_next = (gc < 31) ? hval(1, gc + 1) : 0.f;
        float s = disv(gr, gc) * hc_cur;
        if (gr > 0)  s = fmaf(disv(gr - 1, gc), hval(0, gc), s);
        if (gr < 31) s = fmaf(disv(gr + 1, gc), hval(2, gc), s);
        if (gc > 0)  s = fmaf(disv(gr, gc - 1), hc_prev, s);
        if (gc < 31) s = fmaf(disv(gr, gc + 1), hc_next, s);
        hstage[gc][t] = __float2half(disv(gr, gc) * s);
        hc_prev = hc_cur; hc_cur = hc_next;
    }
    __syncthreads();

    __half* ob = out + ((size_t)b * NNODES + gr * 32) * 256;
    #pragma unroll
    for (int i = 0; i < 4; ++i) {
        int u = i * 256 + t;
        int row = u >> 5, blk = u & 31;
        *(uint4*)(ob + (size_t)row * 256 + blk * 8) =
            *(uint4*)(&hstage[row][blk * 8]);
    }
}

// ---------------------------------------------------------------------------
// Fused layers 2+3, PERSISTENT:  t3 = (relu(agg1@W2^T + rs*b2)) @ W3^T
// 148 CTAs x 512 threads loop over 2048 tiles (M=128 nodes of one batch).
// W streams as k128 chunks (3-stage cyclic cp.async pipeline that never
// restarts); A for tile t+1 prefetched inside the idx==4 group of tile t.
// h2 (128x256) lives only in smem.
// ---------------------------------------------------------------------------
#define OFF_BIAS 0
#define OFF_A    1024
#define OFF_H    (1024 + 65536)
#define OFF_W    (1024 + 2 * 65536)
#define WSTG     32768
#define SMEM23   (OFF_W + 3 * WSTG)

__global__ __launch_bounds__(512, 1)
void gemm23_kernel(const __half* __restrict__ A,
                   const __half* __restrict__ W2h,
                   const __half* __restrict__ W3h,
                   const float* __restrict__ b2,
                   __half* __restrict__ out) {
    extern __shared__ char smem[];
    const int t = threadIdx.x, warp = t >> 5, lane = t & 31;
    const int g4 = lane >> 2, l4 = lane & 3;
    const int warpM = (warp >> 2) * 32, warpN = (warp & 3) * 32;
    const uint32_t sb = (uint32_t)__cvta_generic_to_shared(smem);
    float* biasS = (float*)(smem + OFF_BIAS);

    if (t < 256) biasS[t] = b2[t];

    const __half* Wsrcs[3] = { W2h, W2h + (size_t)128 * 256, W3h };

    // fill helpers (caller commits the group)
    auto fillW = [&](int cidx, int st) {   // cidx = chunk 0..5
        const __half* Wsrc = Wsrcs[cidx >> 1];
        const int c = cidx & 1;
        #pragma unroll
        for (int i = 0; i < 4; ++i) {
            int u = i * 512 + t, row = u >> 4, blk = u & 15;
            cpa16(sb + OFF_W + st * WSTG + row * 256 + (((blk ^ (row & 7)) << 4)),
                  Wsrc + (size_t)row * 256 + c * 128 + blk * 8);
        }
    };
    auto fillA = [&](int tile) {
        const __half* Ab = A + ((size_t)(tile >> 3) * NNODES + (tile & 7) * 128) * KDIM;
        #pragma unroll
        for (int i = 0; i < 8; ++i) {
            int u = i * 512 + t, row = u >> 5, blk = u & 31;
            cpa16(sb + OFF_A + row * 512 + (((blk ^ (row & 7)) << 4)),
                  Ab + (size_t)row * 256 + blk * 8);
        }
    };

    // ldmatrix address precompute (tile-invariant)
    uint32_t aBase[2]; int aX[2];
    #pragma unroll
    for (int mi = 0; mi < 2; ++mi) {
        int r = warpM + mi * 16 + (lane & 15);
        aBase[mi] = (uint32_t)r * 512;
        aX[mi] = r & 7;
    }
    const int lblk = lane >> 4;
    const int bqw = lane >> 3, brw = lane & 7;
    const int bcb = (bqw & 1);
    uint32_t bRow[2]; int bX[2];
    #pragma unroll
    for (int nj = 0; nj < 2; ++nj) {
        int row = warpN + nj * 16 + ((bqw & 2) ? 8 : 0) + brw;
        bRow[nj] = (uint32_t)row * 256;
        bX[nj] = row & 7;
    }

    float acc[2][4][4];

    // prologue: A(tile0) + W chunk0 in one group, W chunk1 in the next
    int tile0 = blockIdx.x;
    fillA(tile0); fillW(0, 0);
    asm volatile("cp.async.commit_group;");
    fillW(1, 1);
    asm volatile("cp.async.commit_group;");

    for (int tile = tile0; tile < NTILES; tile += NCTA) {
        const int mb = tile & 7, b = tile >> 3;
        int ntile = tile + NCTA;
        if (ntile >= NTILES) ntile = tile0;   // harmless wrap prefetch

        for (int idx = 0; idx < 6; ++idx) {
            const int st = idx % 3, ch = idx & 1, pass = idx >> 1;
            const bool ph2 = (idx >= 4);
            const uint32_t aOff = ph2 ? (sb + OFF_H) : (sb + OFF_A);

            // fill(idx) done; fill(idx+1) stays in flight
            asm volatile("cp.async.wait_group 1;");
            __syncthreads();

            // issue group for idx+2 (cyclic across tiles); A rides the idx4 group
            fillW((idx + 2) % 6, (idx + 2) % 3);
            if (idx == 4) fillA(ntile);
            asm volatile("cp.async.commit_group;");

            if (ch == 0) {
                #pragma unroll
                for (int mi = 0; mi < 2; ++mi)
                    #pragma unroll
                    for (int ni = 0; ni < 4; ++ni)
                        #pragma unroll
                        for (int q = 0; q < 4; ++q) acc[mi][ni][q] = 0.f;
            }

            const uint32_t wBase = sb + OFF_W + st * WSTG;
            #pragma unroll
            for (int s = 0; s < 8; ++s) {
                const int kb = ch * 16 + s * 2 + lblk;
                uint32_t af[2][4], bf[2][4];
                #pragma unroll
                for (int mi = 0; mi < 2; ++mi)
                    ldsm4(af[mi], aOff + aBase[mi] + (((kb ^ aX[mi]) << 4)));
                #pragma unroll
                for (int nj = 0; nj < 2; ++nj) {
                    int colblk = s * 2 + bcb;
                    ldsm4(bf[nj], wBase + bRow[nj] + (((colblk ^ bX[nj]) << 4)));
                }
                #pragma unroll
                for (int mi = 0; mi < 2; ++mi)
                    #pragma unroll
                    for (int ni = 0; ni < 4; ++ni) {
                        uint32_t b0 = bf[ni >> 1][(ni & 1) * 2];
                        uint32_t b1 = bf[ni >> 1][(ni & 1) * 2 + 1];
                        asm volatile(
                            "mma.sync.aligned.m16n8k16.row.col.f32.f16.f16.f32 "
                            "{%0,%1,%2,%3},{%4,%5,%6,%7},{%8,%9},{%0,%1,%2,%3};\n"
                            : "+f"(acc[mi][ni][0]), "+f"(acc[mi][ni][1]),
                              "+f"(acc[mi][ni][2]), "+f"(acc[mi][ni][3])
                            : "r"(af[mi][0]), "r"(af[mi][1]),
                              "r"(af[mi][2]), "r"(af[mi][3]),
                              "r"(b0), "r"(b1));
                    }
            }

            if (ch == 1) {
                if (!ph2) {
                    // h2 epilogue: relu(acc + rs*b2) -> swizzled smem
                    #pragma unroll
                    for (int mi = 0; mi < 2; ++mi)
                        #pragma unroll
                        for (int r = 0; r < 2; ++r) {
                            int m = warpM + mi * 16 + g4 + 8 * r;
                            int node = mb * 128 + m;
                            float rs = rowsumv(node >> 5, node & 31);
                            #pragma unroll
                            for (int ni = 0; ni < 4; ++ni) {
                                int col = pass * 128 + warpN + ni * 8 + 2 * l4;
                                float vx = fmaxf(fmaf(rs, biasS[col],     acc[mi][ni][2 * r    ]), 0.f);
                                float vy = fmaxf(fmaf(rs, biasS[col + 1], acc[mi][ni][2 * r + 1]), 0.f);
                                uint32_t off = OFF_H + m * 512 +
                                               (((col >> 3) ^ (m & 7)) << 4) + ((col * 2) & 15);
                                *(__half2*)(smem + off) = __floats2half2_rn(vx, vy);
                            }
                        }
                } else {
                    // t3 epilogue: plain store
                    #pragma unroll
                    for (int mi = 0; mi < 2; ++mi)
                        #pragma unroll
                        for (int r = 0; r < 2; ++r) {
                            int m = warpM + mi * 16 + g4 + 8 * r;
                            int node = mb * 128 + m;
                            __half* op = out + ((size_t)b * NNODES + node) * 128;
                            #pragma unroll
                            for (int ni = 0; ni < 4; ++ni) {
                                int n = warpN + ni * 8 + 2 * l4;
                                *(__half2*)(op + n) =
                                    __floats2half2_rn(acc[mi][ni][2 * r], acc[mi][ni][2 * r + 1]);
                            }
                        }
                }
            }
        }
    }
    // drain outstanding prefetches before exit
    asm volatile("cp.async.wait_group 0;");
    __syncthreads();
}

// ---------------------------------------------------------------------------
// Fused aggregation + classifier partial, register-direct, Wc in fp32:
// CTA = (grid row gr, group of 4 batches), 256 threads.
// ---------------------------------------------------------------------------
__global__ __launch_bounds__(256)
void agg_cls_kernel(const __half* __restrict__ tin,
                    const float* __restrict__ b3,
                    const float* __restrict__ Wc,
                    float* __restrict__ part) {
    const int gr = blockIdx.x, bg = blockIdx.y, t = threadIdx.x;
    float acc[10][4] = {};

    #pragma unroll
    for (int s2 = 0; s2 < 2; ++s2) {
        const int u = s2 * 256 + t;             // 512 slots: node-col x q
        const int gc = u >> 4, q = u & 15;
        const float dC = disv(gr, gc);
        const float dU = (gr > 0)  ? disv(gr - 1, gc) : 0.f;
        const float dD = (gr < 31) ? disv(gr + 1, gc) : 0.f;
        const float dL = (gc > 0)  ? disv(gr, gc - 1) : 0.f;
        const float dR = (gc < 31) ? disv(gr, gc + 1) : 0.f;
        const float rs = rowsumv(gr, gc);
        const float4 bl0 = *(const float4*)(b3 + q * 8);
        const float4 bl1 = *(const float4*)(b3 + q * 8 + 4);

        float h3f[4][8];
        #pragma unroll
        for (int g = 0; g < 4; ++g) {
            const int b = bg * 4 + g;
            const __half* p = tin + ((size_t)b * NNODES + gr * 32 + gc) * 128 + q * 8;
            float s[8] = {};
            h8fma(s, *(const uint4*)p, dC);
            if (dU != 0.f) h8fma(s, *(const uint4*)(p - 32 * 128), dU);
            if (dD != 0.f) h8fma(s, *(const uint4*)(p + 32 * 128), dD);
            if (dL != 0.f) h8fma(s, *(const uint4*)(p - 128), dL);
            if (dR != 0.f) h8fma(s, *(const uint4*)(p + 128), dR);
            h3f[g][0] = fmaxf(fmaf(rs, bl0.x, dC * s[0]), 0.f);
            h3f[g][1] = fmaxf(fmaf(rs, bl0.y, dC * s[1]), 0.f);
            h3f[g][2] = fmaxf(fmaf(rs, bl0.z, dC * s[2]), 0.f);
            h3f[g][3] = fmaxf(fmaf(rs, bl0.w, dC * s[3]), 0.f);
            h3f[g][4] = fmaxf(fmaf(rs, bl1.x, dC * s[4]), 0.f);
            h3f[g][5] = fmaxf(fmaf(rs, bl1.y, dC * s[5]), 0.f);
            h3f[g][6] = fmaxf(fmaf(rs, bl1.z, dC * s[6]), 0.f);
            h3f[g][7] = fmaxf(fmaf(rs, bl1.w, dC * s[7]), 0.f);
        }

        // classifier: fp32 Wc read directly (no cvt), 2 float4 per class
        const float* wp = Wc + (size_t)gr * 4096 + gc * 128 + q * 8;
        #pragma unroll
        for (int c = 0; c < 10; ++c) {
            const float4 wa = *(const float4*)(wp + (size_t)c * 131072);
            const float4 wb = *(const float4*)(wp + (size_t)c * 131072 + 4);
            #pragma unroll
            for (int g = 0; g < 4; ++g) {
                float a = fmaf(h3f[g][0], wa.x, h3f[g][1] * wa.y);
                a = fmaf(h3f[g][2], wa.z, fmaf(h3f[g][3], wa.w, a));
                a = fmaf(h3f[g][4], wb.x, fmaf(h3f[g][5], wb.y, a));
                a = fmaf(h3f[g][6], wb.z, fmaf(h3f[g][7], wb.w, a));
                acc[c][g] += a;
            }
        }
    }

    #pragma unroll
    for (int c = 0; c < 10; c++)
        #pragma unroll
        for (int g = 0; g < 4; g++) {
            float v = acc[c][g];
            for (int o = 16; o; o >>= 1) v += __shfl_down_sync(0xffffffffu, v, o);
            acc[c][g] = v;
        }
    __shared__ float red[8][40];
    if ((t & 31) == 0) {
        int w = t >> 5;
        #pragma unroll
        for (int c = 0; c < 10; c++)
            #pragma unroll
            for (int g = 0; g < 4; g++) red[w][c * 4 + g] = acc[c][g];
    }
    __syncthreads();
    if (t < 40) {
        float s = 0.f;
        #pragma unroll
        for (int w = 0; w < 8; w++) s += red[w][t];
        part[gr * 2560 + bg * 40 + t] = s;
    }
}

__global__ void cls_final_kernel(const float* __restrict__ part,
                                 const float* __restrict__ bc,
                                 float* __restrict__ out) {
    int i = blockIdx.x * 256 + threadIdx.x;
    if (i >= 2560) return;
    int b = i / 10, c = i % 10;
    int bg = b >> 2, g = b & 3;
    float s = bc[c];
    #pragma unroll
    for (int gr = 0; gr < 32; gr++)
        s += part[gr * 2560 + bg * 40 + c * 4 + g];
    out[i] = s;
}

// ---------------------------------------------------------------------------
extern "C" void kernel_launch(void* const* d_in, const int* in_sizes, int n_in,
                              void* d_out, int out_size) {
    const float* x  = (const float*)d_in[0];
    const float* W1 = (const float*)d_in[1];
    const float* b1 = (const float*)d_in[2];
    const float* W2 = (const float*)d_in[3];
    const float* b2 = (const float*)d_in[4];
    const float* W3 = (const float*)d_in[5];
    const float* b3 = (const float*)d_in[6];
    const float* Wc = (const float*)d_in[7];
    const float* bc = (const float*)d_in[8];
    float* out = (float*)d_out;

    __half *buf1, *buf2, *w;
    float *part;
    cudaGetSymbolAddress((void**)&buf1, g_b1);
    cudaGetSymbolAddress((void**)&buf2, g_b2);
    cudaGetSymbolAddress((void**)&w,   g_w);
    cudaGetSymbolAddress((void**)&part, g_part);

    cudaFuncSetAttribute(gemm23_kernel,
                         cudaFuncAttributeMaxDynamicSharedMemorySize, SMEM23);

    convert_w_kernel<<<384, 256>>>(W2, W3, w);
    // layer1 (fused through aggregation): x -> agg1 (buf1)
    layer1_kernel<<<dim3(GRID_W, BATCH), 256>>>(x, W1, b1, buf1);
    // fused layers 2+3, persistent: agg1 -> t3 (buf2); h2 lives only in smem
    gemm23_kernel<<<NCTA, 512, SMEM23>>>(buf1, w, w + 65536, b2, buf2);
    // fused h3 aggregation + classifier partial, register-direct, fp32 Wc
    agg_cls_kernel<<<dim3(GRID_W, 64), 256>>>(buf2, b3, Wc, part);
    cls_final_kernel<<<10, 256>>>(part, bc, out);
}

// round 16
// speedup vs baseline: 1.0595x; 1.0595x over previous
#include <cuda_runtime.h>
#include <cuda_fp16.h>
#include <cstdint>

#define GRID_W 32
#define NNODES 1024
#define BATCH 256
#define KDIM 256
#define NTILES 2048
#define NCTA 148

// Scratch (device globals: no allocations allowed)
__device__ __half g_b1[BATCH * NNODES * 256];          // agg1
__device__ __half g_b2[BATCH * NNODES * 256];          // t3
__device__ __half g_w[65536 + 32768 + 1310720];        // fp16 W2|W3|Wc
__device__ float  g_part[32 * 2560];

// ---------------------------------------------------------------------------
// Stencil weights: adj = D^-1/2 (A+I) D^-1/2, deg in {3,4,5}
// ---------------------------------------------------------------------------
__device__ __forceinline__ float disv(int i, int j) {
    int deg = 1 + (i > 0) + (i < GRID_W - 1) + (j > 0) + (j < GRID_W - 1);
    return deg == 5 ? 0.4472135954999579f
         : (deg == 4 ? 0.5f : 0.5773502691896258f);
}
__device__ __forceinline__ float rowsumv(int i, int j) {
    float d = disv(i, j);
    float s = d;
    if (i > 0)          s += disv(i - 1, j);
    if (i < GRID_W - 1) s += disv(i + 1, j);
    if (j > 0)          s += disv(i, j - 1);
    if (j < GRID_W - 1) s += disv(i, j + 1);
    return d * s;
}
__device__ __forceinline__ void h8fma(float s[8], uint4 u, float w) {
    __half2 h0 = *(__half2*)&u.x, h1 = *(__half2*)&u.y;
    __half2 h2 = *(__half2*)&u.z, h3 = *(__half2*)&u.w;
    float2 f;
    f = __half22float2(h0); s[0] = fmaf(w, f.x, s[0]); s[1] = fmaf(w, f.y, s[1]);
    f = __half22float2(h1); s[2] = fmaf(w, f.x, s[2]); s[3] = fmaf(w, f.y, s[3]);
    f = __half22float2(h2); s[4] = fmaf(w, f.x, s[4]); s[5] = fmaf(w, f.y, s[5]);
    f = __half22float2(h3); s[6] = fmaf(w, f.x, s[6]); s[7] = fmaf(w, f.y, s[7]);
}
__device__ __forceinline__ void ldsm4(uint32_t r[4], uint32_t addr) {
    asm volatile("ldmatrix.sync.aligned.m8n8.x4.shared.b16 {%0,%1,%2,%3}, [%4];"
                 : "=r"(r[0]), "=r"(r[1]), "=r"(r[2]), "=r"(r[3]) : "r"(addr));
}
__device__ __forceinline__ void cpa16(uint32_t dst, const void* src) {
    asm volatile("cp.async.cg.shared.global [%0], [%1], 16;" :: "r"(dst), "l"(src));
}

// ---------------------------------------------------------------------------
// Pre-convert weights fp32 -> fp16 (W2 | W3 | Wc packed)
// ---------------------------------------------------------------------------
__global__ void convert_w_kernel(const float* __restrict__ W2,
                                 const float* __restrict__ W3,
                                 const float* __restrict__ Wc,
                                 __half* __restrict__ o) {
    int i = blockIdx.x * 256 + threadIdx.x;
    if (i < 65536)   o[i] = __float2half(W2[i]);
    if (i < 32768)   o[65536 + i] = __float2half(W3[i]);
    if (i < 1310720) o[98304 + i] = __float2half(Wc[i]);
}

// ---------------------------------------------------------------------------
// Layer 1 fused through aggregation: agg1 = adj @ relu(adj@(x~W1)+rs*b1)
// ---------------------------------------------------------------------------
__global__ void layer1_kernel(const float* __restrict__ x,
                              const float* __restrict__ W1,
                              const float* __restrict__ b1,
                              __half* __restrict__ out) {
    const int gr = blockIdx.x, b = blockIdx.y, t = threadIdx.x;
    __shared__ float aggg[3][32][3];
    __shared__ float rs_s[3][32];
    __shared__ __half hstage[32][256];

    if (t < 96) {
        const int f = t >> 5, gc = t & 31;
        #pragma unroll
        for (int r = 0; r < 3; ++r) {
            int row = gr - 1 + r;
            float v = 0.f;
            if (row >= 0 && row < GRID_W) {
                const float* xp = x + ((size_t)(b * 3 + f)) * NNODES;
                float dm = disv(row, gc);
                float a = dm * xp[row * 32 + gc];
                if (row > 0)  a = fmaf(disv(row - 1, gc), xp[(row - 1) * 32 + gc], a);
                if (row < 31) a = fmaf(disv(row + 1, gc), xp[(row + 1) * 32 + gc], a);
                if (gc > 0)   a = fmaf(disv(row, gc - 1), xp[row * 32 + gc - 1], a);
                if (gc < 31)  a = fmaf(disv(row, gc + 1), xp[row * 32 + gc + 1], a);
                v = dm * a;
            }
            aggg[r][gc][f] = v;
            if (f == 0) rs_s[r][gc] = (row >= 0 && row < GRID_W) ? rowsumv(row, gc) : 0.f;
        }
    }
    __syncthreads();

    const float w0 = W1[t * 3 + 0], w1 = W1[t * 3 + 1], w2 = W1[t * 3 + 2];
    const float bb = b1[t];

    auto hval = [&](int r, int gc) {
        float v = fmaf(aggg[r][gc][0], w0,
                  fmaf(aggg[r][gc][1], w1,
                  fmaf(aggg[r][gc][2], w2, rs_s[r][gc] * bb)));
        return fmaxf(v, 0.f);
    };

    float hc_prev = 0.f, hc_cur = hval(1, 0), hc_next;
    #pragma unroll 4
    for (int gc = 0; gc < 32; ++gc) {
        hc_next = (gc < 31) ? hval(1, gc + 1) : 0.f;
        float s = disv(gr, gc) * hc_cur;
        if (gr > 0)  s = fmaf(disv(gr - 1, gc), hval(0, gc), s);
        if (gr < 31) s = fmaf(disv(gr + 1, gc), hval(2, gc), s);
        if (gc > 0)  s = fmaf(disv(gr, gc - 1), hc_prev, s);
        if (gc < 31) s = fmaf(disv(gr, gc + 1), hc_next, s);
        hstage[gc][t] = __float2half(disv(gr, gc) * s);
        hc_prev = hc_cur; hc_cur = hc_next;
    }
    __syncthreads();

    __half* ob = out + ((size_t)b * NNODES + gr * 32) * 256;
    #pragma unroll
    for (int i = 0; i < 4; ++i) {
        int u = i * 256 + t;
        int row = u >> 5, blk = u & 31;
        *(uint4*)(ob + (size_t)row * 256 + blk * 8) =
            *(uint4*)(&hstage[row][blk * 8]);
    }
}

// ---------------------------------------------------------------------------
// Fused layers 2+3, PERSISTENT:  t3 = (relu(agg1@W2^T + rs*b2)) @ W3^T
// 148 CTAs x 512 threads loop over 2048 tiles; 3-stage cyclic cp.async W
// pipeline that never restarts; A(tile+1) prefetched in the idx==4 group.
// h2 (128x256) lives only in smem.
// ---------------------------------------------------------------------------
#define OFF_BIAS 0
#define OFF_A    1024
#define OFF_H    (1024 + 65536)
#define OFF_W    (1024 + 2 * 65536)
#define WSTG     32768
#define SMEM23   (OFF_W + 3 * WSTG)

__global__ __launch_bounds__(512, 1)
void gemm23_kernel(const __half* __restrict__ A,
                   const __half* __restrict__ W2h,
                   const __half* __restrict__ W3h,
                   const float* __restrict__ b2,
                   __half* __restrict__ out) {
    extern __shared__ char smem[];
    const int t = threadIdx.x, warp = t >> 5, lane = t & 31;
    const int g4 = lane >> 2, l4 = lane & 3;
    const int warpM = (warp >> 2) * 32, warpN = (warp & 3) * 32;
    const uint32_t sb = (uint32_t)__cvta_generic_to_shared(smem);
    float* biasS = (float*)(smem + OFF_BIAS);

    if (t < 256) biasS[t] = b2[t];

    const __half* Wsrcs[3] = { W2h, W2h + (size_t)128 * 256, W3h };

    auto fillW = [&](int cidx, int st) {   // caller commits the group
        const __half* Wsrc = Wsrcs[cidx >> 1];
        const int c = cidx & 1;
        #pragma unroll
        for (int i = 0; i < 4; ++i) {
            int u = i * 512 + t, row = u >> 4, blk = u & 15;
            cpa16(sb + OFF_W + st * WSTG + row * 256 + (((blk ^ (row & 7)) << 4)),
                  Wsrc + (size_t)row * 256 + c * 128 + blk * 8);
        }
    };
    auto fillA = [&](int tile) {
        const __half* Ab = A + ((size_t)(tile >> 3) * NNODES + (tile & 7) * 128) * KDIM;
        #pragma unroll
        for (int i = 0; i < 8; ++i) {
            int u = i * 512 + t, row = u >> 5, blk = u & 31;
            cpa16(sb + OFF_A + row * 512 + (((blk ^ (row & 7)) << 4)),
                  Ab + (size_t)row * 256 + blk * 8);
        }
    };

    uint32_t aBase[2]; int aX[2];
    #pragma unroll
    for (int mi = 0; mi < 2; ++mi) {
        int r = warpM + mi * 16 + (lane & 15);
        aBase[mi] = (uint32_t)r * 512;
        aX[mi] = r & 7;
    }
    const int lblk = lane >> 4;
    const int bqw = lane >> 3, brw = lane & 7;
    const int bcb = (bqw & 1);
    uint32_t bRow[2]; int bX[2];
    #pragma unroll
    for (int nj = 0; nj < 2; ++nj) {
        int row = warpN + nj * 16 + ((bqw & 2) ? 8 : 0) + brw;
        bRow[nj] = (uint32_t)row * 256;
        bX[nj] = row & 7;
    }

    float acc[2][4][4];

    int tile0 = blockIdx.x;
    fillA(tile0); fillW(0, 0);
    asm volatile("cp.async.commit_group;");
    fillW(1, 1);
    asm volatile("cp.async.commit_group;");

    for (int tile = tile0; tile < NTILES; tile += NCTA) {
        const int mb = tile & 7, b = tile >> 3;
        int ntile = tile + NCTA;
        if (ntile >= NTILES) ntile = tile0;   // harmless wrap prefetch

        for (int idx = 0; idx < 6; ++idx) {
            const int st = idx % 3, ch = idx & 1, pass = idx >> 1;
            const bool ph2 = (idx >= 4);
            const uint32_t aOff = ph2 ? (sb + OFF_H) : (sb + OFF_A);

            asm volatile("cp.async.wait_group 1;");
            __syncthreads();

            fillW((idx + 2) % 6, (idx + 2) % 3);
            if (idx == 4) fillA(ntile);
            asm volatile("cp.async.commit_group;");

            if (ch == 0) {
                #pragma unroll
                for (int mi = 0; mi < 2; ++mi)
                    #pragma unroll
                    for (int ni = 0; ni < 4; ++ni)
                        #pragma unroll
                        for (int q = 0; q < 4; ++q) acc[mi][ni][q] = 0.f;
            }

            const uint32_t wBase = sb + OFF_W + st * WSTG;
            #pragma unroll
            for (int s = 0; s < 8; ++s) {
                const int kb = ch * 16 + s * 2 + lblk;
                uint32_t af[2][4], bf[2][4];
                #pragma unroll
                for (int mi = 0; mi < 2; ++mi)
                    ldsm4(af[mi], aOff + aBase[mi] + (((kb ^ aX[mi]) << 4)));
                #pragma unroll
                for (int nj = 0; nj < 2; ++nj) {
                    int colblk = s * 2 + bcb;
                    ldsm4(bf[nj], wBase + bRow[nj] + (((colblk ^ bX[nj]) << 4)));
                }
                #pragma unroll
                for (int mi = 0; mi < 2; ++mi)
                    #pragma unroll
                    for (int ni = 0; ni < 4; ++ni) {
                        uint32_t b0 = bf[ni >> 1][(ni & 1) * 2];
                        uint32_t b1 = bf[ni >> 1][(ni & 1) * 2 + 1];
                        asm volatile(
                            "mma.sync.aligned.m16n8k16.row.col.f32.f16.f16.f32 "
                            "{%0,%1,%2,%3},{%4,%5,%6,%7},{%8,%9},{%0,%1,%2,%3};\n"
                            : "+f"(acc[mi][ni][0]), "+f"(acc[mi][ni][1]),
                              "+f"(acc[mi][ni][2]), "+f"(acc[mi][ni][3])
                            : "r"(af[mi][0]), "r"(af[mi][1]),
                              "r"(af[mi][2]), "r"(af[mi][3]),
                              "r"(b0), "r"(b1));
                    }
            }

            if (ch == 1) {
                if (!ph2) {
                    #pragma unroll
                    for (int mi = 0; mi < 2; ++mi)
                        #pragma unroll
                        for (int r = 0; r < 2; ++r) {
                            int m = warpM + mi * 16 + g4 + 8 * r;
                            int node = mb * 128 + m;
                            float rs = rowsumv(node >> 5, node & 31);
                            #pragma unroll
                            for (int ni = 0; ni < 4; ++ni) {
                                int col = pass * 128 + warpN + ni * 8 + 2 * l4;
                                float vx = fmaxf(fmaf(rs, biasS[col],     acc[mi][ni][2 * r    ]), 0.f);
                                float vy = fmaxf(fmaf(rs, biasS[col + 1], acc[mi][ni][2 * r + 1]), 0.f);
                                uint32_t off = OFF_H + m * 512 +
                                               (((col >> 3) ^ (m & 7)) << 4) + ((col * 2) & 15);
                                *(__half2*)(smem + off) = __floats2half2_rn(vx, vy);
                            }
                        }
                } else {
                    #pragma unroll
                    for (int mi = 0; mi < 2; ++mi)
                        #pragma unroll
                        for (int r = 0; r < 2; ++r) {
                            int m = warpM + mi * 16 + g4 + 8 * r;
                            int node = mb * 128 + m;
                            __half* op = out + ((size_t)b * NNODES + node) * 128;
                            #pragma unroll
                            for (int ni = 0; ni < 4; ++ni) {
                                int n = warpN + ni * 8 + 2 * l4;
                                *(__half2*)(op + n) =
                                    __floats2half2_rn(acc[mi][ni][2 * r], acc[mi][ni][2 * r + 1]);
                            }
                        }
                }
            }
        }
    }
    asm volatile("cp.async.wait_group 0;");
    __syncthreads();
}

// ---------------------------------------------------------------------------
// Fused aggregation + classifier partial, register-direct (R14 version):
// fp16 Wc, one uint4 per class per slot.  CTA = (gr, 4-batch group), 256 thr.
// ---------------------------------------------------------------------------
__global__ __launch_bounds__(256)
void agg_cls_kernel(const __half* __restrict__ tin,
                    const float* __restrict__ b3,
                    const __half* __restrict__ Wc,
                    float* __restrict__ part) {
    const int gr = blockIdx.x, bg = blockIdx.y, t = threadIdx.x;
    float acc[10][4] = {};

    #pragma unroll
    for (int s2 = 0; s2 < 2; ++s2) {
        const int u = s2 * 256 + t;             // 512 slots: node-col x q
        const int gc = u >> 4, q = u & 15;
        const float dC = disv(gr, gc);
        const float dU = (gr > 0)  ? disv(gr - 1, gc) : 0.f;
        const float dD = (gr < 31) ? disv(gr + 1, gc) : 0.f;
        const float dL = (gc > 0)  ? disv(gr, gc - 1) : 0.f;
        const float dR = (gc < 31) ? disv(gr, gc + 1) : 0.f;
        const float rs = rowsumv(gr, gc);
        const float4 bl0 = *(const float4*)(b3 + q * 8);
        const float4 bl1 = *(const float4*)(b3 + q * 8 + 4);

        float h3f[4][8];
        #pragma unroll
        for (int g = 0; g < 4; ++g) {
            const int b = bg * 4 + g;
            const __half* p = tin + ((size_t)b * NNODES + gr * 32 + gc) * 128 + q * 8;
            float s[8] = {};
            h8fma(s, *(const uint4*)p, dC);
            if (dU != 0.f) h8fma(s, *(const uint4*)(p - 32 * 128), dU);
            if (dD != 0.f) h8fma(s, *(const uint4*)(p + 32 * 128), dD);
            if (dL != 0.f) h8fma(s, *(const uint4*)(p - 128), dL);
            if (dR != 0.f) h8fma(s, *(const uint4*)(p + 128), dR);
            h3f[g][0] = fmaxf(fmaf(rs, bl0.x, dC * s[0]), 0.f);
            h3f[g][1] = fmaxf(fmaf(rs, bl0.y, dC * s[1]), 0.f);
            h3f[g][2] = fmaxf(fmaf(rs, bl0.z, dC * s[2]), 0.f);
            h3f[g][3] = fmaxf(fmaf(rs, bl0.w, dC * s[3]), 0.f);
            h3f[g][4] = fmaxf(fmaf(rs, bl1.x, dC * s[4]), 0.f);
            h3f[g][5] = fmaxf(fmaf(rs, bl1.y, dC * s[5]), 0.f);
            h3f[g][6] = fmaxf(fmaf(rs, bl1.z, dC * s[6]), 0.f);
            h3f[g][7] = fmaxf(fmaf(rs, bl1.w, dC * s[7]), 0.f);
        }

        const __half* wp = Wc + (size_t)gr * 4096 + gc * 128 + q * 8;
        #pragma unroll
        for (int c = 0; c < 10; ++c) {
            uint4 w = *(const uint4*)(wp + (size_t)c * 131072);
            float2 w0 = __half22float2(*(__half2*)&w.x);
            float2 w1 = __half22float2(*(__half2*)&w.y);
            float2 w2 = __half22float2(*(__half2*)&w.z);
            float2 w3 = __half22float2(*(__half2*)&w.w);
            #pragma unroll
            for (int g = 0; g < 4; ++g) {
                float a = fmaf(h3f[g][0], w0.x, h3f[g][1] * w0.y);
                a = fmaf(h3f[g][2], w1.x, fmaf(h3f[g][3], w1.y, a));
                a = fmaf(h3f[g][4], w2.x, fmaf(h3f[g][5], w2.y, a));
                a = fmaf(h3f[g][6], w3.x, fmaf(h3f[g][7], w3.y, a));
                acc[c][g] += a;
            }
        }
    }

    #pragma unroll
    for (int c = 0; c < 10; c++)
        #pragma unroll
        for (int g = 0; g < 4; g++) {
            float v = acc[c][g];
            for (int o = 16; o; o >>= 1) v += __shfl_down_sync(0xffffffffu, v, o);
            acc[c][g] = v;
        }
    __shared__ float red[8][40];
    if ((t & 31) == 0) {
        int w = t >> 5;
        #pragma unroll
        for (int c = 0; c < 10; c++)
            #pragma unroll
            for (int g = 0; g < 4; g++) red[w][c * 4 + g] = acc[c][g];
    }
    __syncthreads();
    if (t < 40) {
        float s = 0.f;
        #pragma unroll
        for (int w = 0; w < 8; w++) s += red[w][t];
        part[gr * 2560 + bg * 40 + t] = s;
    }
}

__global__ void cls_final_kernel(const float* __restrict__ part,
                                 const float* __restrict__ bc,
                                 float* __restrict__ out) {
    int i = blockIdx.x * 256 + threadIdx.x;
    if (i >= 2560) return;
    int b = i / 10, c = i % 10;
    int bg = b >> 2, g = b & 3;
    float s = bc[c];
    #pragma unroll
    for (int gr = 0; gr < 32; gr++)
        s += part[gr * 2560 + bg * 40 + c * 4 + g];
    out[i] = s;
}

// ---------------------------------------------------------------------------
extern "C" void kernel_launch(void* const* d_in, const int* in_sizes, int n_in,
                              void* d_out, int out_size) {
    const float* x  = (const float*)d_in[0];
    const float* W1 = (const float*)d_in[1];
    const float* b1 = (const float*)d_in[2];
    const float* W2 = (const float*)d_in[3];
    const float* b2 = (const float*)d_in[4];
    const float* W3 = (const float*)d_in[5];
    const float* b3 = (const float*)d_in[6];
    const float* Wc = (const float*)d_in[7];
    const float* bc = (const float*)d_in[8];
    float* out = (float*)d_out;

    __half *buf1, *buf2, *w;
    float *part;
    cudaGetSymbolAddress((void**)&buf1, g_b1);
    cudaGetSymbolAddress((void**)&buf2, g_b2);
    cudaGetSymbolAddress((void**)&w,   g_w);
    cudaGetSymbolAddress((void**)&part, g_part);

    cudaFuncSetAttribute(gemm23_kernel,
                         cudaFuncAttributeMaxDynamicSharedMemorySize, SMEM23);

    convert_w_kernel<<<5120, 256>>>(W2, W3, Wc, w);
    // layer1 (fused through aggregation): x -> agg1 (buf1)
    layer1_kernel<<<dim3(GRID_W, BATCH), 256>>>(x, W1, b1, buf1);
    // fused layers 2+3, persistent: agg1 -> t3 (buf2); h2 lives only in smem
    gemm23_kernel<<<NCTA, 512, SMEM23>>>(buf1, w, w + 65536, b2, buf2);
    // fused h3 aggregation + classifier partial, register-direct (fp16 Wc)
    agg_cls_kernel<<<dim3(GRID_W, 64), 256>>>(buf2, b3, w + 98304, part);
    cls_final_kernel<<<10, 256>>>(part, bc, out);
}